// round 17
// baseline (speedup 1.0000x reference)
#include <cuda_runtime.h>
#include <cuda_bf16.h>
#include <cstdint>

#define D 64
#define NUM_REL 32
#define MAXB 131072
#define GROUP 128
#define MAX_GROUPS (MAXB / GROUP + NUM_REL)   // 1056
#define THREADS 128
#define BUCKET_BLOCKS 128
#define WORK_BLOCKS (BUCKET_BLOCKS + NUM_REL) // 160

// dynamic smem layout (bytes)
#define SM_IDX  0                      // 128 ints (phase 1: s_count/s_base/s_last)
#define SM_AHI  1024                   // 128 rows x 128 B (bf16 hi) 16 KB (phase1: Rtmp)
#define SM_ALO  (SM_AHI + 16384)       // 16 KB
#define SM_BHI  (SM_ALO + 16384)       // 8 KB
#define SM_BLO  (SM_BHI + 8192)        // 8 KB
#define SMEM_TOTAL (SM_BLO + 8192)     // 50176 B

// Scratch (static device globals — zero-initialized at module load)
__device__ int g_counts[NUM_REL];
__device__ int g_n[NUM_REL];
__device__ int g_table[MAX_GROUPS];
__device__ int g_idx[NUM_REL * MAXB];
__device__ int g_done;
__device__ int g_flag;
__device__ int g_pass;
// pre-split, pre-swizzled B smem image per relation: [hi:0..511 | lo:512..1023]
__device__ uint4 g_Bimg[NUM_REL * 1024];

// ---------------------------------------------------------------------------
// helpers
// ---------------------------------------------------------------------------
__device__ __forceinline__ uint32_t smem_u32(const void* p) {
    uint32_t a;
    asm("{ .reg .u64 t; cvta.to.shared.u64 t, %1; cvt.u32.u64 %0, t; }"
        : "=r"(a) : "l"(p));
    return a;
}
__device__ __forceinline__ void split2(float x0, float x1, uint32_t& hi, uint32_t& lo) {
    __nv_bfloat162 hv = __floats2bfloat162_rn(x0, x1);
    __nv_bfloat162 lv = __floats2bfloat162_rn(x0 - __bfloat162float(hv.x),
                                              x1 - __bfloat162float(hv.y));
    hi = *reinterpret_cast<uint32_t*>(&hv);
    lo = *reinterpret_cast<uint32_t*>(&lv);
}
__device__ __forceinline__ void ldsm_x4(uint32_t addr, uint32_t& r0, uint32_t& r1,
                                        uint32_t& r2, uint32_t& r3) {
    asm volatile("ldmatrix.sync.aligned.m8n8.x4.shared.b16 {%0,%1,%2,%3}, [%4];"
                 : "=r"(r0), "=r"(r1), "=r"(r2), "=r"(r3) : "r"(addr));
}
__device__ __forceinline__ void mma_bf16(float* c, const uint32_t* a,
                                         uint32_t b0, uint32_t b1) {
    asm volatile(
        "mma.sync.aligned.m16n8k16.row.col.f32.bf16.bf16.f32 "
        "{%0,%1,%2,%3}, {%4,%5,%6,%7}, {%8,%9}, {%0,%1,%2,%3};"
        : "+f"(c[0]), "+f"(c[1]), "+f"(c[2]), "+f"(c[3])
        : "r"(a[0]), "r"(a[1]), "r"(a[2]), "r"(a[3]), "r"(b0), "r"(b1));
}

// ---------------------------------------------------------------------------
// ONE fused kernel: bucket + prep + plan + score.
// Blocks 0..127: bucket (2 x int4 per thread). Blocks 128..159: B-image prep.
// Ticket: last worker block builds the plan, fences, raises g_flag.
// ALL blocks spin on g_flag, then run the verified R12 score core (with the
// e1 gather hoisted to 16 in-flight LDGs). The 1056th block past the spin
// resets flag/counters for the next graph replay.
// Residency guarantee: lb(128,4) + 4x50KB smem + 4x128x128 regs -> 4 blocks/SM
// -> 592 resident >= 160 worker blocks -> no deadlock.
// ---------------------------------------------------------------------------
__global__ void __launch_bounds__(THREADS, 4)
fused_kernel(const float* __restrict__ e1g,
             const float* __restrict__ e2g,
             const int*   __restrict__ rels,
             const float* __restrict__ relw,
             float* __restrict__ out, int B)
{
    extern __shared__ __align__(1024) char smem[];
    const uint32_t sb = smem_u32(smem);
    const int bid  = (int)blockIdx.x;
    const int t    = threadIdx.x;
    const int lane = t & 31;

    // phase-1 smem aliases (released before score phase by the spin sync)
    int* s_count = reinterpret_cast<int*>(smem);          // 32 ints
    int* s_base  = reinterpret_cast<int*>(smem) + 32;     // 32 ints
    int* s_flagv = reinterpret_cast<int*>(smem) + 64;     // s_last
    float* Rtmp  = reinterpret_cast<float*>(smem + SM_AHI);

    // =============== phase 1: bucket / prep (worker blocks only) ===========
    if (bid < BUCKET_BLOCKS) {
        if (t < NUM_REL) s_count[t] = 0;
        __syncthreads();

        const int nv4 = B >> 2;
        int rv[8], lp[8];
        bool valid[2];
        #pragma unroll
        for (int h = 0; h < 2; h++) {
            const int i4 = bid * 256 + h * 128 + t;
            valid[h] = (i4 < nv4);
            int4 v = valid[h] ? reinterpret_cast<const int4*>(rels)[i4]
                              : make_int4(0, 0, 0, 0);
            rv[h * 4 + 0] = v.x; rv[h * 4 + 1] = v.y;
            rv[h * 4 + 2] = v.z; rv[h * 4 + 3] = v.w;
            const unsigned am = __ballot_sync(0xffffffffu, valid[h]);
            if (valid[h]) {
                #pragma unroll
                for (int e = 0; e < 4; e++) {
                    const int k = h * 4 + e;
                    const unsigned mask   = __match_any_sync(am, rv[k]);
                    const int      leader = __ffs(mask) - 1;
                    const int      rank   = __popc(mask & ((1u << lane) - 1));
                    int            base   = 0;
                    if (lane == leader) base = atomicAdd(&s_count[rv[k]], __popc(mask));
                    base = __shfl_sync(am, base, leader);
                    lp[k] = base + rank;
                }
            }
        }
        __syncthreads();
        if (t < NUM_REL) s_base[t] = atomicAdd(&g_counts[t], s_count[t]);
        __syncthreads();
        #pragma unroll
        for (int h = 0; h < 2; h++) {
            if (valid[h]) {
                const int i4 = bid * 256 + h * 128 + t;
                #pragma unroll
                for (int e = 0; e < 4; e++) {
                    const int k = h * 4 + e;
                    g_idx[rv[k] * MAXB + s_base[rv[k]] + lp[k]] = i4 * 4 + e;
                }
            }
        }
    } else if (bid < WORK_BLOCKS) {
        // ---- prep: B image for relation r ----
        const int r = bid - BUCKET_BLOCKS;
        {
            const float4* src = reinterpret_cast<const float4*>(relw + r * (D * D));
            float4* dst = reinterpret_cast<float4*>(Rtmp);
            #pragma unroll
            for (int i = t; i < (D * D) / 4; i += THREADS) dst[i] = src[i];
        }
        __syncthreads();
        {
            const int n = t & 63;
            const int cbase = (t >> 6) * 4;          // 4 chunks per thread
            #pragma unroll
            for (int j = 0; j < 4; j++) {
                const int c = cbase + j;
                uint32_t hi[4], lo[4];
                #pragma unroll
                for (int q = 0; q < 4; q++) {
                    const int k = c * 8 + q * 2;
                    split2(Rtmp[k * D + n], Rtmp[(k + 1) * D + n], hi[q], lo[q]);
                }
                const int e = n * 8 + (c ^ (n & 7));
                g_Bimg[r * 1024 + e]       = make_uint4(hi[0], hi[1], hi[2], hi[3]);
                g_Bimg[r * 1024 + 512 + e] = make_uint4(lo[0], lo[1], lo[2], lo[3]);
            }
        }
    }

    // =============== ticket + plan (worker blocks) ==========================
    if (bid < WORK_BLOCKS) {
        __threadfence();
        __syncthreads();
        if (t == 0) {
            int ticket = atomicAdd(&g_done, 1);
            s_flagv[0] = (ticket == WORK_BLOCKS - 1);
        }
        __syncthreads();
        if (s_flagv[0]) {
            if (t < 32) {
                int n = atomicAdd(&g_counts[t], 0);
                g_n[t] = n;
                g_counts[t] = 0;
                int ng = (n + GROUP - 1) / GROUP;
                int s = ng;
                #pragma unroll
                for (int o = 1; o < 32; o <<= 1) {
                    int v = __shfl_up_sync(0xffffffffu, s, o);
                    if (t >= o) s += v;
                }
                int start = s - ng;
                int total = __shfl_sync(0xffffffffu, s, 31);
                for (int g = 0; g < ng; g++) g_table[start + g] = t | (g << 8);
                for (int j = total + t; j < MAX_GROUPS; j += 32) g_table[j] = -1;
            }
            __syncthreads();
            if (t == 0) {
                __threadfence();
                atomicExch(&g_flag, 1);
            }
        }
    }

    // =============== spin until plan published ==============================
    if (t == 0) {
        while (atomicAdd(&g_flag, 0) == 0) __nanosleep(64);
        const int p = atomicAdd(&g_pass, 1);
        if (p == (int)gridDim.x - 1) {      // everyone has passed the spin
            g_flag = 0; g_pass = 0; g_done = 0;
        }
    }
    __syncthreads();                         // also releases phase-1 smem

    // =============== score phase (verified R12 core + hoisted e1 MLP) ======
    int* s_idx = reinterpret_cast<int*>(smem + SM_IDX);

    const int item = g_table[bid];
    if (item < 0) return;
    const int r    = item & 255;
    const int grp  = item >> 8;
    const int cnt0 = g_n[r] - grp * GROUP;
    const int cnt  = cnt0 < GROUP ? cnt0 : GROUP;
    const int* __restrict__ idx = g_idx + r * MAXB + grp * GROUP;

    const int b = idx[t < cnt ? t : cnt - 1];
    s_idx[t] = b;

    // issue all 16 e1 LDG.128s first (MLP=16, hides L2 latency)
    const float4* p1 = reinterpret_cast<const float4*>(e1g) + b * (D / 4);
    float4 fv[16];
    #pragma unroll
    for (int c = 0; c < 16; c++) fv[c] = p1[c];

    // B staging: coalesced copy of pre-split swizzled image (16 KB)
    {
        const uint4* src = g_Bimg + r * 1024;
        uint4* dst = reinterpret_cast<uint4*>(smem + SM_BHI);
        #pragma unroll
        for (int it = 0; it < 8; it++) dst[t + it * THREADS] = src[t + it * THREADS];
    }

    // A staging: split e1 values, swizzled stores
    {
        const int m = t;
        #pragma unroll
        for (int c = 0; c < 8; c++) {
            float4 f0 = fv[2 * c];
            float4 f1 = fv[2 * c + 1];
            uint32_t h0, l0, h1, l1, h2, l2, h3, l3;
            split2(f0.x, f0.y, h0, l0);
            split2(f0.z, f0.w, h1, l1);
            split2(f1.x, f1.y, h2, l2);
            split2(f1.z, f1.w, h3, l3);
            const uint32_t off = (uint32_t)(m * 128 + ((c ^ (m & 7)) << 4));
            *reinterpret_cast<uint4*>(smem + SM_AHI + off) = make_uint4(h0, h1, h2, h3);
            *reinterpret_cast<uint4*>(smem + SM_ALO + off) = make_uint4(l0, l1, l2, l3);
        }
    }
    __syncthreads();

    // MMA mainloop (byte-identical to round 12)
    const int w = t >> 5;

    float acc[2][8][4];
    #pragma unroll
    for (int mt = 0; mt < 2; mt++)
        #pragma unroll
        for (int nt = 0; nt < 8; nt++)
            #pragma unroll
            for (int q = 0; q < 4; q++) acc[mt][nt][q] = 0.0f;

    #pragma unroll
    for (int ks = 0; ks < 4; ks++) {
        uint32_t ah[2][4], al[2][4];
        #pragma unroll
        for (int mt = 0; mt < 2; mt++) {
            const int row   = 32 * w + 16 * mt + (lane & 15);
            const int chunk = 2 * ks + (lane >> 4);
            const uint32_t off =
                (uint32_t)(row * 128 + ((chunk ^ (row & 7)) << 4));
            ldsm_x4(sb + SM_AHI + off, ah[mt][0], ah[mt][1], ah[mt][2], ah[mt][3]);
            ldsm_x4(sb + SM_ALO + off, al[mt][0], al[mt][1], al[mt][2], al[mt][3]);
        }
        uint32_t bh[8][2], bl[8][2];
        #pragma unroll
        for (int p = 0; p < 4; p++) {
            const int n     = 16 * p + ((lane >> 4) << 3) + (lane & 7);
            const int chunk = 2 * ks + ((lane >> 3) & 1);
            const uint32_t off =
                (uint32_t)(n * 128 + ((chunk ^ (n & 7)) << 4));
            ldsm_x4(sb + SM_BHI + off, bh[2 * p][0], bh[2 * p][1],
                                        bh[2 * p + 1][0], bh[2 * p + 1][1]);
            ldsm_x4(sb + SM_BLO + off, bl[2 * p][0], bl[2 * p][1],
                                        bl[2 * p + 1][0], bl[2 * p + 1][1]);
        }
        #pragma unroll
        for (int mt = 0; mt < 2; mt++)
            #pragma unroll
            for (int nt = 0; nt < 8; nt++) {
                mma_bf16(acc[mt][nt], ah[mt], bh[nt][0], bh[nt][1]);
                mma_bf16(acc[mt][nt], ah[mt], bl[nt][0], bl[nt][1]);
                mma_bf16(acc[mt][nt], al[mt], bh[nt][0], bh[nt][1]);
            }
    }

    // epilogue: dot c-fragments with e2, quad-reduce, store
    {
        const int g  = lane >> 2;
        const int tg = lane & 3;
        #pragma unroll
        for (int mt = 0; mt < 2; mt++) {
            #pragma unroll
            for (int v = 0; v < 2; v++) {
                const int m  = 32 * w + 16 * mt + g + 8 * v;
                const int bm = s_idx[m];
                float p = 0.0f;
                #pragma unroll
                for (int nt = 0; nt < 8; nt++) {
                    const float2 u = *reinterpret_cast<const float2*>(
                        e2g + bm * D + nt * 8 + 2 * tg);
                    p += acc[mt][nt][2 * v]     * u.x;
                    p += acc[mt][nt][2 * v + 1] * u.y;
                }
                p += __shfl_xor_sync(0xffffffffu, p, 1);
                p += __shfl_xor_sync(0xffffffffu, p, 2);
                if (tg == 0 && m < cnt) out[bm] = p;
            }
        }
    }
}

// ---------------------------------------------------------------------------
// kernel_launch
// inputs: embeds1 [B*64] f32, embeds2 [B*64] f32, rels [B] i32,
//         rel_embeds [32*4096] f32 ; output [B] f32
// ---------------------------------------------------------------------------
extern "C" void kernel_launch(void* const* d_in, const int* in_sizes, int n_in,
                              void* d_out, int out_size) {
    const float* e1   = (const float*)d_in[0];
    const float* e2   = (const float*)d_in[1];
    const int*   rels = (const int*)d_in[2];
    const float* relw = (const float*)d_in[3];
    float* out = (float*)d_out;

    const int B = in_sizes[2];

    cudaFuncSetAttribute(fused_kernel,
                         cudaFuncAttributeMaxDynamicSharedMemorySize, SMEM_TOTAL);

    fused_kernel<<<MAX_GROUPS, THREADS, SMEM_TOTAL>>>(e1, e2, rels, relw, out, B);
}